// round 1
// baseline (speedup 1.0000x reference)
#include <cuda_runtime.h>
#include <math.h>

#define BB 16
#define LL 4096
#define PD 512
#define HH 256

// scratch (no allocations allowed)
__device__ unsigned long long g_keys[BB * LL];
__device__ int   g_rank[BB * LL];
__device__ int   g_keptlist[BB * LL];
__device__ int   g_lenkeep[BB];
__device__ float g_fsemb[BB * HH];

// ---------------------------------------------------------------------------
// K_zero: zero the seq_unmasked region of the output (rows >= len_keep must be 0)
// ---------------------------------------------------------------------------
__global__ void k_zero(float4* __restrict__ out) {
    // BB*LL*HH floats = 4,194,304 float4
    size_t n = (size_t)BB * LL * HH / 4;
    size_t i = (size_t)blockIdx.x * blockDim.x + threadIdx.x;
    size_t stride = (size_t)gridDim.x * blockDim.x;
    float4 z = make_float4(0.f, 0.f, 0.f, 0.f);
    for (; i < n; i += stride) out[i] = z;
}

// ---------------------------------------------------------------------------
// K_setup: build sort keys + len_keep per batch row
// ---------------------------------------------------------------------------
__global__ void k_setup(const int* __restrict__ sids,
                        const int* __restrict__ eff_lens,
                        const float* __restrict__ noise) {
    int b = blockIdx.x;
    int eff = eff_lens[b];
    __shared__ int s_ns;
    if (threadIdx.x == 0) s_ns = 0;
    __syncthreads();
    int local = 0;
    for (int l = threadIdx.x; l < LL; l += blockDim.x) {
        bool valid = l < eff;
        int sid  = sids[b * LL + l];
        int prev = (l >= 1) ? sids[b * LL + l - 1] : -1;
        int pp   = (l >= 2) ? sids[b * LL + l - 2] : -1;
        bool seg = valid && (sid != prev);
        bool fst = valid && (l >= 1) && (prev != pp);
        unsigned int bits = (seg || fst) ? 0u : __float_as_uint(noise[b * LL + l]);
        g_keys[b * LL + l] = ((unsigned long long)bits << 12) | (unsigned)l;
        local += seg ? 1 : 0;
    }
    atomicAdd(&s_ns, local);
    __syncthreads();
    if (threadIdx.x == 0) {
        int ns = s_ns;
        float kf = (float)(eff - 2 * ns) * 0.25f;
        g_lenkeep[b] = 2 * ns + (int)truncf(kf);
    }
}

// ---------------------------------------------------------------------------
// K_rank: stable-sort rank via key counting.  rank(l)=l for padding.
// grid (16, BB), block 256
// ---------------------------------------------------------------------------
__global__ void k_rank(const int* __restrict__ eff_lens) {
    __shared__ unsigned long long sk[LL];
    int b = blockIdx.y;
    int eff = eff_lens[b];
    for (int m = threadIdx.x; m < LL; m += blockDim.x)
        sk[m] = (m < eff) ? g_keys[b * LL + m] : ~0ull;
    __syncthreads();
    int l = blockIdx.x * blockDim.x + threadIdx.x;
    if (l >= eff) { g_rank[b * LL + l] = l; return; }
    unsigned long long mk = sk[l];
    int effr = (eff + 7) & ~7;
    int cnt = 0;
    for (int m = 0; m < effr; m += 8) {
#pragma unroll
        for (int i = 0; i < 8; i++)
            cnt += (sk[m + i] < mk) ? 1 : 0;
    }
    g_rank[b * LL + l] = cnt;
}

// ---------------------------------------------------------------------------
// K_scan: per-row prefix sum over kept flags; writes mae_mask, ids_restore,
// unmask_ids and the compact kept-token list.  One block (1024 thr) per row.
// ---------------------------------------------------------------------------
__global__ void k_scan(const int* __restrict__ sids,
                       const int* __restrict__ eff_lens,
                       float* __restrict__ out) {
    int b = blockIdx.x;
    int eff = eff_lens[b];
    int lk = g_lenkeep[b];
    int t = threadIdx.x;
    int base = t * 4;

    int4 rk4 = *(const int4*)&g_rank[b * LL + base];
    int r[4] = {rk4.x, rk4.y, rk4.z, rk4.w};
    bool kept[4];
    int cnt = 0;
#pragma unroll
    for (int i = 0; i < 4; i++) {
        int l = base + i;
        kept[i] = (l < eff) && (r[i] < lk);
        cnt += kept[i] ? 1 : 0;
    }

    int lane = t & 31, wid = t >> 5;
    int inc = cnt;
#pragma unroll
    for (int d = 1; d < 32; d <<= 1) {
        int v = __shfl_up_sync(0xffffffffu, inc, d);
        if (lane >= d) inc += v;
    }
    __shared__ int wsum[32];
    if (lane == 31) wsum[wid] = inc;
    __syncthreads();
    if (wid == 0) {
        int v = wsum[lane];
#pragma unroll
        for (int d = 1; d < 32; d <<= 1) {
            int u = __shfl_up_sync(0xffffffffu, v, d);
            if (lane >= d) v += u;
        }
        wsum[lane] = v;
    }
    __syncthreads();
    int ex = ((wid > 0) ? wsum[wid - 1] : 0) + (inc - cnt);

    const size_t O1 = (size_t)BB * LL * HH;
    const size_t O2 = O1 + (size_t)BB * LL;
    const size_t O3 = O2 + (size_t)BB * LL;
    float* mae = out + O1 + (size_t)b * LL;
    float* rst = out + O2 + (size_t)b * LL;
    float* unm = out + O3 + (size_t)b * LL;

    int p = ex;
#pragma unroll
    for (int i = 0; i < 4; i++) {
        int l = base + i;
        mae[l] = (l < eff && !kept[i]) ? 1.0f : 0.0f;
        rst[l] = (float)(kept[i] ? p : r[i]);
        if (kept[i]) {
            g_keptlist[b * LL + p] = l;
            unm[p] = (float)sids[b * LL + l];
            p++;
        }
        if (l >= lk) unm[l] = -1.0f;   // disjoint from scatter targets (p < lk)
    }
}

// ---------------------------------------------------------------------------
// K_fs: timestep embedding MLP.  One block (256 thr) per batch row.
// ---------------------------------------------------------------------------
__global__ void k_fs(const float* __restrict__ fs,
                     const float* __restrict__ w1, const float* __restrict__ b1,
                     const float* __restrict__ w2, const float* __restrict__ b2) {
    int b = blockIdx.x;
    int t = threadIdx.x;
    __shared__ float tf[256], h1[256];
    if (t < 128) {
        float fr = expf(-9.2103403719761836f * (float)t * (1.0f / 128.0f));
        float arg = fs[b] * fr;
        tf[t] = cosf(arg);
        tf[t + 128] = sinf(arg);
    }
    __syncthreads();
    {
        float s = b1[t];
        for (int i = 0; i < 256; i++) s = fmaf(tf[i], w1[t * 256 + i], s);
        h1[t] = s / (1.0f + expf(-s));   // silu
    }
    __syncthreads();
    {
        float s = b2[t];
        for (int i = 0; i < 256; i++) s = fmaf(h1[i], w2[t * 256 + i], s);
        g_fsemb[b * 256 + t] = s;
    }
}

// ---------------------------------------------------------------------------
// K_gemm: out[b,p,:] = patches[b,kept[p],:] @ W^T + bias + pos[kept[p],:] + fsemb[b,:]
// Only kept rows.  fp32x2 packed FMA (pairs along K).  BM=64, 256 threads,
// per-thread 8 rows x 8 cols.
// ---------------------------------------------------------------------------
#define BM 64
#define KC 32

__global__ void __launch_bounds__(256, 1)
k_gemm(const float* __restrict__ patches, const float* __restrict__ W,
       const float* __restrict__ bias, const float* __restrict__ pos,
       float* __restrict__ out_seq) {
    int b = blockIdx.y;
    int p0 = blockIdx.x * BM;
    int lk = g_lenkeep[b];
    if (p0 >= lk) return;

    __shared__ float2 As2[KC / 2][BM];    // 8 KB   (k-pair major, row minor)
    __shared__ float2 Ws2[KC / 2][HH];    // 32 KB
    __shared__ float  sBF[HH];
    __shared__ int    sKL[BM];

    int t = threadIdx.x;          // 256
    int tcol = t & 31;            // lane -> base column
    int trow = t >> 5;            // warp -> row group (8 rows)

    sBF[t] = bias[t] + g_fsemb[b * HH + t];
    if (t < BM) {
        int p = p0 + t;
        sKL[t] = (p < lk) ? g_keptlist[b * LL + p] : 0;
    }
    __syncthreads();

    unsigned long long acc[8][8];
#pragma unroll
    for (int i = 0; i < 8; i++)
#pragma unroll
        for (int j = 0; j < 8; j++) acc[i][j] = 0ull;

    for (int k0 = 0; k0 < PD; k0 += KC) {
        // A tile: 64 rows x 32 floats = 512 float4, 2 per thread
#pragma unroll
        for (int c = 0; c < 2; c++) {
            int f4id = c * 256 + t;
            int row = f4id >> 3;
            int q   = f4id & 7;
            int kl  = sKL[row];
            float4 v = *(const float4*)&patches[((size_t)b * LL + kl) * PD + k0 + q * 4];
            As2[q * 2][row]     = make_float2(v.x, v.y);
            As2[q * 2 + 1][row] = make_float2(v.z, v.w);
        }
        // W tile: 256 rows x 32 floats = 2048 float4, 8 per thread
#pragma unroll
        for (int c = 0; c < 8; c++) {
            int f4id = c * 256 + t;
            int h = f4id >> 3;
            int q = f4id & 7;
            float4 v = *(const float4*)&W[h * PD + k0 + q * 4];
            Ws2[q * 2][h]     = make_float2(v.x, v.y);
            Ws2[q * 2 + 1][h] = make_float2(v.z, v.w);
        }
        __syncthreads();
#pragma unroll
        for (int k2 = 0; k2 < KC / 2; k2++) {
            unsigned long long a[8], w[8];
#pragma unroll
            for (int i = 0; i < 8; i++)   // warp-uniform -> LDS broadcast
                a[i] = *(const unsigned long long*)&As2[k2][trow * 8 + i];
#pragma unroll
            for (int j = 0; j < 8; j++)   // lane-consecutive -> conflict-free
                w[j] = *(const unsigned long long*)&Ws2[k2][tcol + 32 * j];
#pragma unroll
            for (int i = 0; i < 8; i++)
#pragma unroll
                for (int j = 0; j < 8; j++)
                    asm("fma.rn.f32x2 %0, %1, %2, %0;"
                        : "+l"(acc[i][j]) : "l"(a[i]), "l"(w[j]));
        }
        __syncthreads();
    }

#pragma unroll
    for (int i = 0; i < 8; i++) {
        int p = p0 + trow * 8 + i;
        if (p >= lk) continue;
        int kl = sKL[trow * 8 + i];
#pragma unroll
        for (int j = 0; j < 8; j++) {
            int h = tcol + 32 * j;
            float2 f = *(float2*)&acc[i][j];
            float s = f.x + f.y + sBF[h] + pos[(size_t)kl * HH + h];
            out_seq[(((size_t)b * LL) + p) * HH + h] = s;
        }
    }
}

// ---------------------------------------------------------------------------
extern "C" void kernel_launch(void* const* d_in, const int* in_sizes, int n_in,
                              void* d_out, int out_size) {
    const float* patches = (const float*)d_in[0];
    const int*   sids    = (const int*)  d_in[1];
    const int*   eff     = (const int*)  d_in[2];
    const float* noise   = (const float*)d_in[3];
    const float* fs      = (const float*)d_in[4];
    const float* W       = (const float*)d_in[5];
    const float* bias    = (const float*)d_in[6];
    const float* pos     = (const float*)d_in[7];
    const float* w1      = (const float*)d_in[8];
    const float* b1      = (const float*)d_in[9];
    const float* w2      = (const float*)d_in[10];
    const float* b2      = (const float*)d_in[11];
    float* out = (float*)d_out;

    k_zero<<<4096, 256>>>((float4*)out);
    k_setup<<<BB, 1024>>>(sids, eff, noise);
    k_fs<<<BB, 256>>>(fs, w1, b1, w2, b2);
    k_rank<<<dim3(16, BB), 256>>>(eff);
    k_scan<<<BB, 1024>>>(sids, eff, out);
    k_gemm<<<dim3(17, BB), 256>>>(patches, W, bias, pos, out);

    (void)in_sizes; (void)n_in; (void)out_size;
}

// round 2
// speedup vs baseline: 1.7159x; 1.7159x over previous
#include <cuda_runtime.h>
#include <math.h>

#define BB 16
#define LL 4096
#define PD 512
#define HH 256
#define NB 2048   // rank buckets

// scratch (no allocations allowed)
__device__ int   g_keptlist[BB * LL];
__device__ int   g_lenkeep[BB];
__device__ float g_fsemb[BB * HH];

// ---------------------------------------------------------------------------
// block-wide exclusive scan over one int per thread (1024 threads)
// ---------------------------------------------------------------------------
__device__ __forceinline__ int block_exscan(int v, int* wsum) {
    int lane = threadIdx.x & 31, wid = threadIdx.x >> 5;
    int inc = v;
#pragma unroll
    for (int d = 1; d < 32; d <<= 1) {
        int u = __shfl_up_sync(0xffffffffu, inc, d);
        if (lane >= d) inc += u;
    }
    if (lane == 31) wsum[wid] = inc;
    __syncthreads();
    if (wid == 0) {
        int s = wsum[lane];
#pragma unroll
        for (int d = 1; d < 32; d <<= 1) {
            int u = __shfl_up_sync(0xffffffffu, s, d);
            if (lane >= d) s += u;
        }
        wsum[lane] = s;
    }
    __syncthreads();
    return ((wid > 0) ? wsum[wid - 1] : 0) + (inc - v);
}

// ---------------------------------------------------------------------------
// k_prep: fused setup + bucket-rank + scan.  One block (1024 thr) per row.
// Produces mae_mask, ids_restore, unmask_ids outputs + keptlist/lenkeep.
// ---------------------------------------------------------------------------
__global__ void __launch_bounds__(1024, 1)
k_prep(const int* __restrict__ sids, const int* __restrict__ eff_lens,
       const float* __restrict__ noise, float* __restrict__ out) {
    __shared__ unsigned long long s_keys[LL];  // 32 KB (bucket-sorted keys)
    __shared__ int s_hist[NB + 1];             // 8 KB  (counts -> excl starts)
    __shared__ int s_wsum[32];
    __shared__ int s_ns;

    int b = blockIdx.x;
    int t = threadIdx.x;
    int eff = eff_lens[b];
    int base = t * 4;

    // zero histogram
    s_hist[t] = 0;
    if (t < NB + 1 - 1024) s_hist[1024 + t] = 0;
    if (t == 0) { s_hist[NB] = 0; s_ns = 0; }

    // load my 4 sids/noise + 2 predecessors
    int4  sd4 = *(const int4*)  &sids [b * LL + base];
    float4 nz4 = *(const float4*)&noise[b * LL + base];
    int sm1 = (base >= 1) ? sids[b * LL + base - 1] : -1;
    int sm2 = (base >= 2) ? sids[b * LL + base - 2] : -1;
    __syncthreads();

    int   sd[6] = {sm2, sm1, sd4.x, sd4.y, sd4.z, sd4.w};
    float nz[4] = {nz4.x, nz4.y, nz4.z, nz4.w};

    unsigned long long key[4];
    int bid[4], slot[4];
    int nseg = 0;
#pragma unroll
    for (int i = 0; i < 4; i++) {
        int l = base + i;
        bool valid = l < eff;
        bool seg = valid && (sd[i + 2] != sd[i + 1]);
        bool fst = valid && (l >= 1) && (sd[i + 1] != sd[i]);
        nseg += seg ? 1 : 0;
        float v = (seg || fst) ? 0.0f : nz[i];
        unsigned int bits = __float_as_uint(v);
        key[i] = ((unsigned long long)bits << 12) | (unsigned)l;
        bid[i] = min(NB - 1, (int)(v * (float)NB));
        if (valid) slot[i] = atomicAdd(&s_hist[bid[i]], 1);
    }
    // segment count -> s_ns
    {
        int v = nseg;
#pragma unroll
        for (int d = 16; d > 0; d >>= 1) v += __shfl_down_sync(0xffffffffu, v, d);
        if ((t & 31) == 0 && v) atomicAdd(&s_ns, v);
    }
    __syncthreads();

    int ns = s_ns;
    int lk = 2 * ns + (int)((float)(eff - 2 * ns) * 0.25f);

    // exclusive scan of histogram (2 entries per thread)
    int c0 = s_hist[2 * t], c1 = s_hist[2 * t + 1];
    int ex = block_exscan(c0 + c1, s_wsum);
    s_hist[2 * t] = ex;
    s_hist[2 * t + 1] = ex + c0;
    if (t == 1023) s_hist[NB] = ex + c0 + c1;   // == eff
    __syncthreads();

    // scatter keys into bucket-sorted order
#pragma unroll
    for (int i = 0; i < 4; i++) {
        int l = base + i;
        if (l < eff) s_keys[s_hist[bid[i]] + slot[i]] = key[i];
    }
    __syncthreads();

    // rank = bucket_start + (# keys in bucket < mine);  padding: rank = l
    int r[4];
    bool kept[4];
    int cnt = 0;
#pragma unroll
    for (int i = 0; i < 4; i++) {
        int l = base + i;
        if (l < eff) {
            int lo = s_hist[bid[i]], hi = s_hist[bid[i] + 1];
            int c = 0;
            for (int m = lo; m < hi; m++) c += (s_keys[m] < key[i]) ? 1 : 0;
            r[i] = lo + c;
        } else {
            r[i] = l;
        }
        kept[i] = (l < eff) && (r[i] < lk);
        cnt += kept[i] ? 1 : 0;
    }
    __syncthreads();

    int p = block_exscan(cnt, s_wsum);

    const size_t O1 = (size_t)BB * LL * HH;
    const size_t O2 = O1 + (size_t)BB * LL;
    const size_t O3 = O2 + (size_t)BB * LL;
    float* mae = out + O1 + (size_t)b * LL;
    float* rst = out + O2 + (size_t)b * LL;
    float* unm = out + O3 + (size_t)b * LL;

#pragma unroll
    for (int i = 0; i < 4; i++) {
        int l = base + i;
        mae[l] = (l < eff && !kept[i]) ? 1.0f : 0.0f;
        rst[l] = (float)(kept[i] ? p : r[i]);
        if (kept[i]) {
            g_keptlist[b * LL + p] = l;
            unm[p] = (float)sd[i + 2];
            p++;
        }
        if (l >= lk) unm[l] = -1.0f;   // disjoint from scatter targets (p < lk)
    }
    if (t == 0) g_lenkeep[b] = lk;
}

// ---------------------------------------------------------------------------
// k_zero_tail: zero seq_unmasked rows >= len_keep (everything else is written)
// ---------------------------------------------------------------------------
__global__ void k_zero_tail(float4* __restrict__ out) {
    int b = blockIdx.y;
    int lk = g_lenkeep[b];
    size_t basef4 = ((size_t)b * LL + lk) * (HH / 4);
    size_t n = (size_t)(LL - lk) * (HH / 4);
    float4 z = make_float4(0.f, 0.f, 0.f, 0.f);
    size_t stride = (size_t)gridDim.x * blockDim.x;
    for (size_t i = (size_t)blockIdx.x * blockDim.x + threadIdx.x; i < n; i += stride)
        out[basef4 + i] = z;
}

// ---------------------------------------------------------------------------
// k_fs: timestep MLP, warp-per-output (coalesced weight reads). 1 block / row.
// ---------------------------------------------------------------------------
__global__ void k_fs(const float* __restrict__ fs,
                     const float* __restrict__ w1, const float* __restrict__ b1,
                     const float* __restrict__ w2, const float* __restrict__ b2) {
    int b = blockIdx.x;
    int t = threadIdx.x, lane = t & 31, wid = t >> 5;   // 8 warps
    __shared__ float tf[256], h1[256];
    if (t < 128) {
        float fr = expf(-9.2103403719761836f * (float)t * (1.0f / 128.0f));
        float arg = fs[b] * fr;
        tf[t] = cosf(arg);
        tf[t + 128] = sinf(arg);
    }
    __syncthreads();
    for (int h = wid; h < 256; h += 8) {
        float4 a0 = *(const float4*)&w1[h * 256 + lane * 8];
        float4 a1 = *(const float4*)&w1[h * 256 + lane * 8 + 4];
        float s = tf[lane*8+0]*a0.x + tf[lane*8+1]*a0.y + tf[lane*8+2]*a0.z + tf[lane*8+3]*a0.w
                + tf[lane*8+4]*a1.x + tf[lane*8+5]*a1.y + tf[lane*8+6]*a1.z + tf[lane*8+7]*a1.w;
#pragma unroll
        for (int d = 16; d > 0; d >>= 1) s += __shfl_down_sync(0xffffffffu, s, d);
        if (lane == 0) { s += b1[h]; h1[h] = s / (1.0f + expf(-s)); }
    }
    __syncthreads();
    for (int h = wid; h < 256; h += 8) {
        float4 a0 = *(const float4*)&w2[h * 256 + lane * 8];
        float4 a1 = *(const float4*)&w2[h * 256 + lane * 8 + 4];
        float s = h1[lane*8+0]*a0.x + h1[lane*8+1]*a0.y + h1[lane*8+2]*a0.z + h1[lane*8+3]*a0.w
                + h1[lane*8+4]*a1.x + h1[lane*8+5]*a1.y + h1[lane*8+6]*a1.z + h1[lane*8+7]*a1.w;
#pragma unroll
        for (int d = 16; d > 0; d >>= 1) s += __shfl_down_sync(0xffffffffu, s, d);
        if (lane == 0) g_fsemb[b * 256 + h] = s + b2[h];
    }
}

// ---------------------------------------------------------------------------
// k_gemm: out[b,p,n0:n0+128] = patches[b,kept[p],:] @ W^T + bias + pos + fsemb
// BM=64 x BN=128 tiles, 8x4 f32x2 accumulators per thread, 2 blocks/SM.
// ---------------------------------------------------------------------------
#define BM 64
#define BN 128
#define KC 32

__global__ void __launch_bounds__(256, 2)
k_gemm(const float* __restrict__ patches, const float* __restrict__ W,
       const float* __restrict__ bias, const float* __restrict__ pos,
       float* __restrict__ out_seq) {
    int b  = blockIdx.z;
    int n0 = blockIdx.y * BN;
    int p0 = blockIdx.x * BM;
    int lk = g_lenkeep[b];
    if (p0 >= lk) return;

    __shared__ float2 As2[KC / 2][BM + 1];   // padded: conflict-free stores
    __shared__ float2 Ws2[KC / 2][BN + 1];
    __shared__ float  sBF[BN];
    __shared__ int    sKL[BM];

    int t = threadIdx.x;
    int tcol = t & 31;
    int trow = t >> 5;

    if (t < BN) sBF[t] = bias[n0 + t] + g_fsemb[b * HH + n0 + t];
    if (t < BM) {
        int p = p0 + t;
        sKL[t] = (p < lk) ? g_keptlist[b * LL + p] : 0;
    }
    __syncthreads();

    unsigned long long acc[8][4];
#pragma unroll
    for (int i = 0; i < 8; i++)
#pragma unroll
        for (int j = 0; j < 4; j++) acc[i][j] = 0ull;

    for (int k0 = 0; k0 < PD; k0 += KC) {
        // A tile: 64 rows x 32 floats = 512 float4, 2 per thread
#pragma unroll
        for (int c = 0; c < 2; c++) {
            int f4id = c * 256 + t;
            int row = f4id >> 3;
            int q   = f4id & 7;
            float4 v = *(const float4*)&patches[((size_t)b * LL + sKL[row]) * PD + k0 + q * 4];
            As2[q * 2][row]     = make_float2(v.x, v.y);
            As2[q * 2 + 1][row] = make_float2(v.z, v.w);
        }
        // W tile: 128 rows x 32 floats = 1024 float4, 4 per thread
#pragma unroll
        for (int c = 0; c < 4; c++) {
            int f4id = c * 256 + t;
            int h = f4id >> 3;
            int q = f4id & 7;
            float4 v = *(const float4*)&W[(size_t)(n0 + h) * PD + k0 + q * 4];
            Ws2[q * 2][h]     = make_float2(v.x, v.y);
            Ws2[q * 2 + 1][h] = make_float2(v.z, v.w);
        }
        __syncthreads();
#pragma unroll
        for (int k2 = 0; k2 < KC / 2; k2++) {
            unsigned long long a[8], w[4];
#pragma unroll
            for (int i = 0; i < 8; i++)   // warp-uniform -> LDS broadcast
                a[i] = *(const unsigned long long*)&As2[k2][trow * 8 + i];
#pragma unroll
            for (int j = 0; j < 4; j++)   // lane-consecutive -> conflict-free
                w[j] = *(const unsigned long long*)&Ws2[k2][tcol + 32 * j];
#pragma unroll
            for (int i = 0; i < 8; i++)
#pragma unroll
                for (int j = 0; j < 4; j++)
                    asm("fma.rn.f32x2 %0, %1, %2, %0;"
                        : "+l"(acc[i][j]) : "l"(a[i]), "l"(w[j]));
        }
        __syncthreads();
    }

#pragma unroll
    for (int i = 0; i < 8; i++) {
        int p = p0 + trow * 8 + i;
        if (p >= lk) continue;
        int kl = sKL[trow * 8 + i];
#pragma unroll
        for (int j = 0; j < 4; j++) {
            int hc = tcol + 32 * j;
            float2 f = *(float2*)&acc[i][j];
            float s = f.x + f.y + sBF[hc] + pos[(size_t)kl * HH + n0 + hc];
            out_seq[(((size_t)b * LL) + p) * HH + n0 + hc] = s;
        }
    }
}

// ---------------------------------------------------------------------------
extern "C" void kernel_launch(void* const* d_in, const int* in_sizes, int n_in,
                              void* d_out, int out_size) {
    const float* patches = (const float*)d_in[0];
    const int*   sids    = (const int*)  d_in[1];
    const int*   eff     = (const int*)  d_in[2];
    const float* noise   = (const float*)d_in[3];
    const float* fs      = (const float*)d_in[4];
    const float* W       = (const float*)d_in[5];
    const float* bias    = (const float*)d_in[6];
    const float* pos     = (const float*)d_in[7];
    const float* w1      = (const float*)d_in[8];
    const float* b1      = (const float*)d_in[9];
    const float* w2      = (const float*)d_in[10];
    const float* b2      = (const float*)d_in[11];
    float* out = (float*)d_out;

    k_prep<<<BB, 1024>>>(sids, eff, noise, out);
    k_fs<<<BB, 256>>>(fs, w1, b1, w2, b2);
    k_zero_tail<<<dim3(192, BB), 256>>>((float4*)out);
    k_gemm<<<dim3(17, 2, BB), 256>>>(patches, W, bias, pos, out);

    (void)in_sizes; (void)n_in; (void)out_size;
}

// round 5
// speedup vs baseline: 2.3339x; 1.3602x over previous
#include <cuda_runtime.h>
#include <cuda_bf16.h>
#include <math.h>
#include <stdint.h>

#define BB 16
#define LL 4096
#define PD 512
#define HH 256
#define NB 2048            // rank buckets
#define MROWS 1152         // max kept rows per batch (9*128)
#define KP 1536            // split-K' = 3 * PD
#define KC2 64             // K' chunk per pipeline stage (bf16)
#define NCH (KP / KC2)     // 24 chunks

// ---------------------------------------------------------------------------
// scratch (static device memory — no allocations allowed)
// ---------------------------------------------------------------------------
__device__ int   g_keptlist[BB * LL];
__device__ int   g_lenkeep[BB];
__device__ float g_fsemb[BB * HH];
__device__ __align__(1024) __nv_bfloat16 g_Ahl[(size_t)BB * MROWS * KP]; // 56.6 MB
__device__ __align__(1024) __nv_bfloat16 g_Whl[(size_t)HH * KP];         // 786 KB

// ---------------------------------------------------------------------------
// PTX helpers (all plain sm_80/90 PTX — no 'a'-gated instructions)
// ---------------------------------------------------------------------------
__device__ __forceinline__ uint32_t smem_u32(const void* p) {
    uint32_t a;
    asm("{ .reg .u64 t; cvta.to.shared.u64 t, %1; cvt.u32.u64 %0, t; }" : "=r"(a) : "l"(p));
    return a;
}
__device__ __forceinline__ void cp16(uint32_t s, const void* g) {
    asm volatile("cp.async.cg.shared.global [%0], [%1], 16;" :: "r"(s), "l"(g));
}
#define CP_COMMIT() asm volatile("cp.async.commit_group;" ::: "memory")

__device__ __forceinline__ void ldsm4(uint32_t* r, uint32_t a) {
    asm volatile("ldmatrix.sync.aligned.m8n8.x4.shared.b16 {%0,%1,%2,%3}, [%4];"
                 : "=r"(r[0]), "=r"(r[1]), "=r"(r[2]), "=r"(r[3]) : "r"(a));
}
__device__ __forceinline__ void mma16816(float* d, const uint32_t* a,
                                         uint32_t b0, uint32_t b1) {
    asm volatile(
        "mma.sync.aligned.m16n8k16.row.col.f32.bf16.bf16.f32 "
        "{%0,%1,%2,%3}, {%4,%5,%6,%7}, {%8,%9}, {%0,%1,%2,%3};"
        : "+f"(d[0]), "+f"(d[1]), "+f"(d[2]), "+f"(d[3])
        : "r"(a[0]), "r"(a[1]), "r"(a[2]), "r"(a[3]), "r"(b0), "r"(b1));
}

// ---------------------------------------------------------------------------
// block-wide exclusive scan over one int per thread (1024 threads)
// ---------------------------------------------------------------------------
__device__ __forceinline__ int block_exscan(int v, int* wsum) {
    int lane = threadIdx.x & 31, wid = threadIdx.x >> 5;
    int inc = v;
#pragma unroll
    for (int d = 1; d < 32; d <<= 1) {
        int u = __shfl_up_sync(0xffffffffu, inc, d);
        if (lane >= d) inc += u;
    }
    if (lane == 31) wsum[wid] = inc;
    __syncthreads();
    if (wid == 0) {
        int s = wsum[lane];
#pragma unroll
        for (int d = 1; d < 32; d <<= 1) {
            int u = __shfl_up_sync(0xffffffffu, s, d);
            if (lane >= d) s += u;
        }
        wsum[lane] = s;
    }
    __syncthreads();
    return ((wid > 0) ? wsum[wid - 1] : 0) + (inc - v);
}

// ---------------------------------------------------------------------------
// k_prep: fused setup + bucket-rank + scan.  One block (1024 thr) per row.
// ---------------------------------------------------------------------------
__global__ void __launch_bounds__(1024, 1)
k_prep(const int* __restrict__ sids, const int* __restrict__ eff_lens,
       const float* __restrict__ noise, float* __restrict__ out) {
    __shared__ unsigned long long s_keys[LL];
    __shared__ int s_hist[NB + 1];
    __shared__ int s_wsum[32];
    __shared__ int s_ns;

    int b = blockIdx.x;
    int t = threadIdx.x;
    int eff = eff_lens[b];
    int base = t * 4;

    s_hist[t] = 0;
    if (t < NB + 1 - 1024) s_hist[1024 + t] = 0;
    if (t == 0) { s_hist[NB] = 0; s_ns = 0; }

    int4  sd4 = *(const int4*)  &sids [b * LL + base];
    float4 nz4 = *(const float4*)&noise[b * LL + base];
    int sm1 = (base >= 1) ? sids[b * LL + base - 1] : -1;
    int sm2 = (base >= 2) ? sids[b * LL + base - 2] : -1;
    __syncthreads();

    int   sd[6] = {sm2, sm1, sd4.x, sd4.y, sd4.z, sd4.w};
    float nz[4] = {nz4.x, nz4.y, nz4.z, nz4.w};

    unsigned long long key[4];
    int bid[4], slot[4];
    int nseg = 0;
#pragma unroll
    for (int i = 0; i < 4; i++) {
        int l = base + i;
        bool valid = l < eff;
        bool seg = valid && (sd[i + 2] != sd[i + 1]);
        bool fst = valid && (l >= 1) && (sd[i + 1] != sd[i]);
        nseg += seg ? 1 : 0;
        float v = (seg || fst) ? 0.0f : nz[i];
        unsigned int bits = __float_as_uint(v);
        key[i] = ((unsigned long long)bits << 12) | (unsigned)l;
        bid[i] = min(NB - 1, (int)(v * (float)NB));
        if (valid) slot[i] = atomicAdd(&s_hist[bid[i]], 1);
    }
    {
        int v = nseg;
#pragma unroll
        for (int d = 16; d > 0; d >>= 1) v += __shfl_down_sync(0xffffffffu, v, d);
        if ((t & 31) == 0 && v) atomicAdd(&s_ns, v);
    }
    __syncthreads();

    int ns = s_ns;
    int lk = 2 * ns + (int)((float)(eff - 2 * ns) * 0.25f);

    int c0 = s_hist[2 * t], c1 = s_hist[2 * t + 1];
    int ex = block_exscan(c0 + c1, s_wsum);
    s_hist[2 * t] = ex;
    s_hist[2 * t + 1] = ex + c0;
    if (t == 1023) s_hist[NB] = ex + c0 + c1;
    __syncthreads();

#pragma unroll
    for (int i = 0; i < 4; i++) {
        int l = base + i;
        if (l < eff) s_keys[s_hist[bid[i]] + slot[i]] = key[i];
    }
    __syncthreads();

    int r[4];
    bool kept[4];
    int cnt = 0;
#pragma unroll
    for (int i = 0; i < 4; i++) {
        int l = base + i;
        if (l < eff) {
            int lo = s_hist[bid[i]], hi = s_hist[bid[i] + 1];
            int c = 0;
            for (int m = lo; m < hi; m++) c += (s_keys[m] < key[i]) ? 1 : 0;
            r[i] = lo + c;
        } else {
            r[i] = l;
        }
        kept[i] = (l < eff) && (r[i] < lk);
        cnt += kept[i] ? 1 : 0;
    }
    __syncthreads();

    int p = block_exscan(cnt, s_wsum);

    const size_t O1 = (size_t)BB * LL * HH;
    const size_t O2 = O1 + (size_t)BB * LL;
    const size_t O3 = O2 + (size_t)BB * LL;
    float* mae = out + O1 + (size_t)b * LL;
    float* rst = out + O2 + (size_t)b * LL;
    float* unm = out + O3 + (size_t)b * LL;

#pragma unroll
    for (int i = 0; i < 4; i++) {
        int l = base + i;
        mae[l] = (l < eff && !kept[i]) ? 1.0f : 0.0f;
        rst[l] = (float)(kept[i] ? p : r[i]);
        if (kept[i]) {
            g_keptlist[b * LL + p] = l;
            unm[p] = (float)sd[i + 2];
            p++;
        }
        if (l >= lk) unm[l] = -1.0f;
    }
    if (t == 0) g_lenkeep[b] = lk;
}

// ---------------------------------------------------------------------------
// k_convW: W fp32 -> triplet bf16 [b_hi, b_hi, b_lo] along K.
// ---------------------------------------------------------------------------
__global__ void k_convW(const float* __restrict__ W) {
    int gid = blockIdx.x * 256 + threadIdx.x;   // 16384 items
    int row = gid >> 6;
    int k0  = (gid & 63) * 8;
    float4 v0 = *(const float4*)&W[(size_t)row * PD + k0];
    float4 v1 = *(const float4*)&W[(size_t)row * PD + k0 + 4];
    float a[8] = {v0.x, v0.y, v0.z, v0.w, v1.x, v1.y, v1.z, v1.w};
    __align__(16) __nv_bfloat16 o[24];
#pragma unroll
    for (int i = 0; i < 8; i++) {
        __nv_bfloat16 h = __float2bfloat16_rn(a[i]);
        __nv_bfloat16 l = __float2bfloat16_rn(a[i] - __bfloat162float(h));
        o[3 * i] = h; o[3 * i + 1] = h; o[3 * i + 2] = l;
    }
    uint4* dst = (uint4*)&g_Whl[(size_t)row * KP + 3 * k0];
    const uint4* src = (const uint4*)o;
    dst[0] = src[0]; dst[1] = src[1]; dst[2] = src[2];
}

// ---------------------------------------------------------------------------
// k_convA: gather kept patch rows -> triplet bf16 [a_hi, a_lo, a_hi]
// ---------------------------------------------------------------------------
__global__ void k_convA(const float* __restrict__ patches) {
    int b = blockIdx.y;
    int lk = g_lenkeep[b];
    int t = threadIdx.x;
    int p = blockIdx.x * 4 + (t >> 6);
    if (p >= lk) return;
    int k0 = (t & 63) * 8;
    int kl = g_keptlist[b * LL + p];
    const float4* src = (const float4*)&patches[((size_t)b * LL + kl) * PD + k0];
    float4 v0 = src[0], v1 = src[1];
    float a[8] = {v0.x, v0.y, v0.z, v0.w, v1.x, v1.y, v1.z, v1.w};
    __align__(16) __nv_bfloat16 o[24];
#pragma unroll
    for (int i = 0; i < 8; i++) {
        __nv_bfloat16 h = __float2bfloat16_rn(a[i]);
        __nv_bfloat16 l = __float2bfloat16_rn(a[i] - __bfloat162float(h));
        o[3 * i] = h; o[3 * i + 1] = l; o[3 * i + 2] = h;
    }
    uint4* dst = (uint4*)&g_Ahl[((size_t)b * MROWS + p) * KP + 3 * k0];
    const uint4* s4 = (const uint4*)o;
    dst[0] = s4[0]; dst[1] = s4[1]; dst[2] = s4[2];
}

// ---------------------------------------------------------------------------
// k_zero_tail: zero seq_unmasked rows >= len_keep
// ---------------------------------------------------------------------------
__global__ void k_zero_tail(float4* __restrict__ out) {
    int b = blockIdx.y;
    int lk = g_lenkeep[b];
    size_t basef4 = ((size_t)b * LL + lk) * (HH / 4);
    size_t n = (size_t)(LL - lk) * (HH / 4);
    float4 z = make_float4(0.f, 0.f, 0.f, 0.f);
    size_t stride = (size_t)gridDim.x * blockDim.x;
    for (size_t i = (size_t)blockIdx.x * blockDim.x + threadIdx.x; i < n; i += stride)
        out[basef4 + i] = z;
}

// ---------------------------------------------------------------------------
// k_fs: timestep MLP, warp-per-output.
// ---------------------------------------------------------------------------
__global__ void k_fs(const float* __restrict__ fs,
                     const float* __restrict__ w1, const float* __restrict__ b1,
                     const float* __restrict__ w2, const float* __restrict__ b2) {
    int b = blockIdx.x;
    int t = threadIdx.x, lane = t & 31, wid = t >> 5;
    __shared__ float tf[256], h1[256];
    if (t < 128) {
        float fr = expf(-9.2103403719761836f * (float)t * (1.0f / 128.0f));
        float arg = fs[b] * fr;
        tf[t] = cosf(arg);
        tf[t + 128] = sinf(arg);
    }
    __syncthreads();
    for (int h = wid; h < 256; h += 8) {
        float4 a0 = *(const float4*)&w1[h * 256 + lane * 8];
        float4 a1 = *(const float4*)&w1[h * 256 + lane * 8 + 4];
        float s = tf[lane*8+0]*a0.x + tf[lane*8+1]*a0.y + tf[lane*8+2]*a0.z + tf[lane*8+3]*a0.w
                + tf[lane*8+4]*a1.x + tf[lane*8+5]*a1.y + tf[lane*8+6]*a1.z + tf[lane*8+7]*a1.w;
#pragma unroll
        for (int d = 16; d > 0; d >>= 1) s += __shfl_down_sync(0xffffffffu, s, d);
        if (lane == 0) { s += b1[h]; h1[h] = s / (1.0f + expf(-s)); }
    }
    __syncthreads();
    for (int h = wid; h < 256; h += 8) {
        float4 a0 = *(const float4*)&w2[h * 256 + lane * 8];
        float4 a1 = *(const float4*)&w2[h * 256 + lane * 8 + 4];
        float s = h1[lane*8+0]*a0.x + h1[lane*8+1]*a0.y + h1[lane*8+2]*a0.z + h1[lane*8+3]*a0.w
                + h1[lane*8+4]*a1.x + h1[lane*8+5]*a1.y + h1[lane*8+6]*a1.z + h1[lane*8+7]*a1.w;
#pragma unroll
        for (int d = 16; d > 0; d >>= 1) s += __shfl_down_sync(0xffffffffu, s, d);
        if (lane == 0) g_fsemb[b * 256 + h] = s + b2[h];
    }
}

// ---------------------------------------------------------------------------
// k_gemm: mma.sync bf16 GEMM.  Block (512 thr, 16 warps) = (batch, M-tile 128),
// N = 256 whole, K' = 1536 in 24 double-buffered cp.async chunks of 64.
// Warp tile 32x64 (warp grid 4 M x 4 N).  Swizzled smem (seg ^= row&7) + ldmatrix.
// Dynamic SMEM layout at 1024-aligned base AB:
//   AB+0     sBF[256] floats
//   AB+1024  sKL[128] ints
//   AB+2048  A buf0 (16 KB), +18432 A buf1, +34816 B buf0 (32 KB), +67584 B buf1
// ---------------------------------------------------------------------------
#define SM_A0 2048
#define SM_B0 34816
#define SMEMSZ (100352 + 1024)

__global__ void __launch_bounds__(512, 1)
k_gemm(const float* __restrict__ bias, const float* __restrict__ pos,
       float* __restrict__ out_seq) {
    extern __shared__ char dsm[];
    int b  = blockIdx.y;
    int p0 = blockIdx.x * 128;
    int lk = g_lenkeep[b];
    if (p0 >= lk) return;

    uint32_t AB = (smem_u32(dsm) + 1023u) & ~1023u;
    char* ABp = dsm + (AB - smem_u32(dsm));
    float* sBF = (float*)(ABp);
    int*   sKL = (int*)(ABp + 1024);

    int t = threadIdx.x;
    int lane = t & 31, wid = t >> 5;
    int wm = wid & 3, wn = wid >> 2;

    if (t < 256) sBF[t] = bias[t] + g_fsemb[b * HH + t];
    if (t < 128) {
        int p = p0 + t;
        sKL[t] = (p < lk) ? g_keptlist[b * LL + p] : 0;
    }

    // ---- cp.async offsets (chunk-invariant, full tile coverage) ----
    // A tile: 128 rows x 128 B = 1024 segs (16 B); 512 thr -> 2 each
    // B tile: 256 rows x 128 B = 2048 segs;        512 thr -> 4 each
    uint32_t aoffS[2]; size_t aoffG[2];
#pragma unroll
    for (int i = 0; i < 2; i++) {
        int sid = t + i * 512;
        int r = sid >> 3, s = sid & 7;
        aoffS[i] = (uint32_t)(r * 128 + ((s ^ (r & 7)) * 16));
        aoffG[i] = (size_t)r * KP + s * 8;
    }
    uint32_t boffS[4]; size_t boffG[4];
#pragma unroll
    for (int i = 0; i < 4; i++) {
        int sid = t + i * 512;
        int r = sid >> 3, s = sid & 7;
        boffS[i] = (uint32_t)(r * 128 + ((s ^ (r & 7)) * 16));
        boffG[i] = (size_t)r * KP + s * 8;
    }

    const __nv_bfloat16* Abase = &g_Ahl[((size_t)b * MROWS + p0) * KP];
    const __nv_bfloat16* Bbase = g_Whl;

    // ---- ldmatrix address components ----
    // A: subtile mt in {0,1}: rows; lanes 0-15 -> rows, lanes>>4 -> k-half
    uint32_t aRB[2], aXP[2];
#pragma unroll
    for (int mt = 0; mt < 2; mt++) {
        int rowA = wm * 32 + mt * 16 + (lane & 15);
        aRB[mt] = AB + SM_A0 + (uint32_t)(rowA * 128);
        aXP[mt] = (uint32_t)((rowA & 7) << 4);
    }
    uint32_t aSG = (uint32_t)((lane >> 4) * 16);
    // B: group g: lanes 0-7 n0-7/k0, 8-15 n0-7/k8, 16-23 n8-15/k0, 24-31 n8-15/k8
    uint32_t bRB[4], bXP[4];
#pragma unroll
    for (int g = 0; g < 4; g++) {
        int rowB = wn * 64 + g * 16 + ((lane >> 4) << 3) + (lane & 7);
        bRB[g] = AB + SM_B0 + (uint32_t)(rowB * 128);
        bXP[g] = (uint32_t)((rowB & 7) << 4);
    }
    uint32_t bSG = (uint32_t)(((lane >> 3) & 1) * 16);

    float acc[2][8][4];
#pragma unroll
    for (int mt = 0; mt < 2; mt++)
#pragma unroll
        for (int nt = 0; nt < 8; nt++)
#pragma unroll
            for (int i = 0; i < 4; i++) acc[mt][nt][i] = 0.f;

    auto copy_chunk = [&](int c) {
        uint32_t ao = AB + SM_A0 + (uint32_t)(c & 1) * 16384u;
        uint32_t bo = AB + SM_B0 + (uint32_t)(c & 1) * 32768u;
        const __nv_bfloat16* Ag = Abase + c * KC2;
        const __nv_bfloat16* Bg = Bbase + c * KC2;
#pragma unroll
        for (int i = 0; i < 2; i++) cp16(ao + aoffS[i], Ag + aoffG[i]);
#pragma unroll
        for (int i = 0; i < 4; i++) cp16(bo + boffS[i], Bg + boffG[i]);
        CP_COMMIT();
    };

    copy_chunk(0);
    copy_chunk(1);

    for (int c = 0; c < NCH; c++) {
        if (c + 1 < NCH) asm volatile("cp.async.wait_group 1;" ::: "memory");
        else             asm volatile("cp.async.wait_group 0;" ::: "memory");
        __syncthreads();
        uint32_t ao = (uint32_t)(c & 1) * 16384u;
        uint32_t bo = (uint32_t)(c & 1) * 32768u;
#pragma unroll
        for (int s = 0; s < 4; s++) {
            uint32_t afr[2][4], bfr[4][4];
#pragma unroll
            for (int mt = 0; mt < 2; mt++)
                ldsm4(afr[mt], aRB[mt] + ao + (((uint32_t)(s * 32) + aSG) ^ aXP[mt]));
#pragma unroll
            for (int g = 0; g < 4; g++)
                ldsm4(bfr[g], bRB[g] + bo + (((uint32_t)(s * 32) + bSG) ^ bXP[g]));
#pragma unroll
            for (int mt = 0; mt < 2; mt++)
#pragma unroll
                for (int nt = 0; nt < 8; nt++)
                    mma16816(acc[mt][nt], afr[mt],
                             bfr[nt >> 1][(nt & 1) * 2], bfr[nt >> 1][(nt & 1) * 2 + 1]);
        }
        if (c + 2 < NCH) {
            __syncthreads();
            copy_chunk(c + 2);
        }
    }

    // ---- epilogue: acc + bias + fsemb + pos -> out ----
#pragma unroll
    for (int mt = 0; mt < 2; mt++) {
        int rbase = wm * 32 + mt * 16 + (lane >> 2);
#pragma unroll
        for (int h = 0; h < 2; h++) {
            int rr = rbase + h * 8;
            int p = p0 + rr;
            if (p < lk) {
                int kl = sKL[rr];
                float* orow = &out_seq[(((size_t)b * LL) + p) * HH];
                const float* prow = &pos[(size_t)kl * HH];
#pragma unroll
                for (int nt = 0; nt < 8; nt++) {
                    int col = wn * 64 + nt * 8 + (lane & 3) * 2;
                    float2 v;
                    v.x = acc[mt][nt][h * 2 + 0] + sBF[col]     + prow[col];
                    v.y = acc[mt][nt][h * 2 + 1] + sBF[col + 1] + prow[col + 1];
                    *(float2*)&orow[col] = v;
                }
            }
        }
    }
}

// ---------------------------------------------------------------------------
extern "C" void kernel_launch(void* const* d_in, const int* in_sizes, int n_in,
                              void* d_out, int out_size) {
    const float* patches = (const float*)d_in[0];
    const int*   sids    = (const int*)  d_in[1];
    const int*   eff     = (const int*)  d_in[2];
    const float* noise   = (const float*)d_in[3];
    const float* fs      = (const float*)d_in[4];
    const float* W       = (const float*)d_in[5];
    const float* bias    = (const float*)d_in[6];
    const float* pos     = (const float*)d_in[7];
    const float* w1      = (const float*)d_in[8];
    const float* b1      = (const float*)d_in[9];
    const float* w2      = (const float*)d_in[10];
    const float* b2      = (const float*)d_in[11];
    float* out = (float*)d_out;

    cudaFuncSetAttribute(k_gemm, cudaFuncAttributeMaxDynamicSharedMemorySize, SMEMSZ);

    k_prep<<<BB, 1024>>>(sids, eff, noise, out);
    k_convW<<<64, 256>>>(W);
    k_fs<<<BB, 256>>>(fs, w1, b1, w2, b2);
    k_convA<<<dim3(288, BB), 256>>>(patches);
    k_zero_tail<<<dim3(192, BB), 256>>>((float4*)out);
    k_gemm<<<dim3(9, BB), 512, SMEMSZ>>>(bias, pos, out);

    (void)in_sizes; (void)n_in; (void)out_size;
}

// round 6
// speedup vs baseline: 2.5901x; 1.1098x over previous
#include <cuda_runtime.h>
#include <cuda_bf16.h>
#include <math.h>
#include <stdint.h>

#define BB 16
#define LL 4096
#define PD 512
#define HH 256
#define NB 2048            // rank buckets
#define NCH 8              // fp32 K chunks of 64

// ---------------------------------------------------------------------------
// scratch (static device memory — no allocations allowed)
// ---------------------------------------------------------------------------
__device__ int   g_keptlist[BB * LL];
__device__ int   g_lenkeep[BB];
__device__ float g_fsemb[BB * HH];
// per chunk c: [Bhi 256x64 | Blo 256x64] flat = 32768 bf16; 8 chunks = 512 KB
__device__ __align__(1024) __nv_bfloat16 g_Bs[8 * 32768];

// ---------------------------------------------------------------------------
// PTX helpers (plain sm_80/90 PTX — no 'a'-gated instructions)
// ---------------------------------------------------------------------------
__device__ __forceinline__ uint32_t smem_u32(const void* p) {
    uint32_t a;
    asm("{ .reg .u64 t; cvta.to.shared.u64 t, %1; cvt.u32.u64 %0, t; }" : "=r"(a) : "l"(p));
    return a;
}
__device__ __forceinline__ void cp16(uint32_t s, const void* g) {
    asm volatile("cp.async.cg.shared.global [%0], [%1], 16;" :: "r"(s), "l"(g));
}
#define CP_COMMIT() asm volatile("cp.async.commit_group;" ::: "memory")

__device__ __forceinline__ void ldsm4(uint32_t* r, uint32_t a) {
    asm volatile("ldmatrix.sync.aligned.m8n8.x4.shared.b16 {%0,%1,%2,%3}, [%4];"
                 : "=r"(r[0]), "=r"(r[1]), "=r"(r[2]), "=r"(r[3]) : "r"(a));
}
__device__ __forceinline__ void mma16816(float* d, const uint32_t* a,
                                         uint32_t b0, uint32_t b1) {
    asm volatile(
        "mma.sync.aligned.m16n8k16.row.col.f32.bf16.bf16.f32 "
        "{%0,%1,%2,%3}, {%4,%5,%6,%7}, {%8,%9}, {%0,%1,%2,%3};"
        : "+f"(d[0]), "+f"(d[1]), "+f"(d[2]), "+f"(d[3])
        : "r"(a[0]), "r"(a[1]), "r"(a[2]), "r"(a[3]), "r"(b0), "r"(b1));
}

// ---------------------------------------------------------------------------
// block-wide exclusive scan over one int per thread (1024 threads)
// ---------------------------------------------------------------------------
__device__ __forceinline__ int block_exscan(int v, int* wsum) {
    int lane = threadIdx.x & 31, wid = threadIdx.x >> 5;
    int inc = v;
#pragma unroll
    for (int d = 1; d < 32; d <<= 1) {
        int u = __shfl_up_sync(0xffffffffu, inc, d);
        if (lane >= d) inc += u;
    }
    if (lane == 31) wsum[wid] = inc;
    __syncthreads();
    if (wid == 0) {
        int s = wsum[lane];
#pragma unroll
        for (int d = 1; d < 32; d <<= 1) {
            int u = __shfl_up_sync(0xffffffffu, s, d);
            if (lane >= d) s += u;
        }
        wsum[lane] = s;
    }
    __syncthreads();
    return ((wid > 0) ? wsum[wid - 1] : 0) + (inc - v);
}

// ---------------------------------------------------------------------------
// k_prep: fused setup + bucket-rank + scan.  One block (1024 thr) per row.
// ---------------------------------------------------------------------------
__global__ void __launch_bounds__(1024, 1)
k_prep(const int* __restrict__ sids, const int* __restrict__ eff_lens,
       const float* __restrict__ noise, float* __restrict__ out) {
    __shared__ unsigned long long s_keys[LL];
    __shared__ int s_hist[NB + 1];
    __shared__ int s_wsum[32];
    __shared__ int s_ns;

    int b = blockIdx.x;
    int t = threadIdx.x;
    int eff = eff_lens[b];
    int base = t * 4;

    s_hist[t] = 0;
    if (t < NB + 1 - 1024) s_hist[1024 + t] = 0;
    if (t == 0) { s_hist[NB] = 0; s_ns = 0; }

    int4  sd4 = *(const int4*)  &sids [b * LL + base];
    float4 nz4 = *(const float4*)&noise[b * LL + base];
    int sm1 = (base >= 1) ? sids[b * LL + base - 1] : -1;
    int sm2 = (base >= 2) ? sids[b * LL + base - 2] : -1;
    __syncthreads();

    int   sd[6] = {sm2, sm1, sd4.x, sd4.y, sd4.z, sd4.w};
    float nz[4] = {nz4.x, nz4.y, nz4.z, nz4.w};

    unsigned long long key[4];
    int bid[4], slot[4];
    int nseg = 0;
#pragma unroll
    for (int i = 0; i < 4; i++) {
        int l = base + i;
        bool valid = l < eff;
        bool seg = valid && (sd[i + 2] != sd[i + 1]);
        bool fst = valid && (l >= 1) && (sd[i + 1] != sd[i]);
        nseg += seg ? 1 : 0;
        float v = (seg || fst) ? 0.0f : nz[i];
        unsigned int bits = __float_as_uint(v);
        key[i] = ((unsigned long long)bits << 12) | (unsigned)l;
        bid[i] = min(NB - 1, (int)(v * (float)NB));
        if (valid) slot[i] = atomicAdd(&s_hist[bid[i]], 1);
    }
    {
        int v = nseg;
#pragma unroll
        for (int d = 16; d > 0; d >>= 1) v += __shfl_down_sync(0xffffffffu, v, d);
        if ((t & 31) == 0 && v) atomicAdd(&s_ns, v);
    }
    __syncthreads();

    int ns = s_ns;
    int lk = 2 * ns + (int)((float)(eff - 2 * ns) * 0.25f);

    int c0 = s_hist[2 * t], c1 = s_hist[2 * t + 1];
    int ex = block_exscan(c0 + c1, s_wsum);
    s_hist[2 * t] = ex;
    s_hist[2 * t + 1] = ex + c0;
    if (t == 1023) s_hist[NB] = ex + c0 + c1;
    __syncthreads();

#pragma unroll
    for (int i = 0; i < 4; i++) {
        int l = base + i;
        if (l < eff) s_keys[s_hist[bid[i]] + slot[i]] = key[i];
    }
    __syncthreads();

    int r[4];
    bool kept[4];
    int cnt = 0;
#pragma unroll
    for (int i = 0; i < 4; i++) {
        int l = base + i;
        if (l < eff) {
            int lo = s_hist[bid[i]], hi = s_hist[bid[i] + 1];
            int c = 0;
            for (int m = lo; m < hi; m++) c += (s_keys[m] < key[i]) ? 1 : 0;
            r[i] = lo + c;
        } else {
            r[i] = l;
        }
        kept[i] = (l < eff) && (r[i] < lk);
        cnt += kept[i] ? 1 : 0;
    }
    __syncthreads();

    int p = block_exscan(cnt, s_wsum);

    const size_t O1 = (size_t)BB * LL * HH;
    const size_t O2 = O1 + (size_t)BB * LL;
    const size_t O3 = O2 + (size_t)BB * LL;
    float* mae = out + O1 + (size_t)b * LL;
    float* rst = out + O2 + (size_t)b * LL;
    float* unm = out + O3 + (size_t)b * LL;

#pragma unroll
    for (int i = 0; i < 4; i++) {
        int l = base + i;
        mae[l] = (l < eff && !kept[i]) ? 1.0f : 0.0f;
        rst[l] = (float)(kept[i] ? p : r[i]);
        if (kept[i]) {
            g_keptlist[b * LL + p] = l;
            unm[p] = (float)sd[i + 2];
            p++;
        }
        if (l >= lk) unm[l] = -1.0f;
    }
    if (t == 0) g_lenkeep[b] = lk;
}

// ---------------------------------------------------------------------------
// k_convW: W fp32 -> per-chunk [Bhi | Blo] bf16.  16384 threads.
// ---------------------------------------------------------------------------
__global__ void k_convW(const float* __restrict__ W) {
    int gid = blockIdx.x * 256 + threadIdx.x;   // 16384
    int row = gid >> 6;          // 0..255
    int g   = gid & 63;          // col group of 8 f32
    int c   = g >> 3;            // chunk
    int cc  = (g & 7) * 8;       // col within chunk
    float4 v0 = *(const float4*)&W[(size_t)row * PD + g * 8];
    float4 v1 = *(const float4*)&W[(size_t)row * PD + g * 8 + 4];
    float a[8] = {v0.x, v0.y, v0.z, v0.w, v1.x, v1.y, v1.z, v1.w};
    __align__(16) __nv_bfloat16 oh[8], ol[8];
#pragma unroll
    for (int i = 0; i < 8; i++) {
        __nv_bfloat16 h = __float2bfloat16_rn(a[i]);
        oh[i] = h;
        ol[i] = __float2bfloat16_rn(a[i] - __bfloat162float(h));
    }
    *(uint4*)&g_Bs[c * 32768 + row * 64 + cc]         = *(const uint4*)oh;
    *(uint4*)&g_Bs[c * 32768 + 16384 + row * 64 + cc] = *(const uint4*)ol;
}

// ---------------------------------------------------------------------------
// k_fs: timestep MLP, warp-per-output.
// ---------------------------------------------------------------------------
__global__ void k_fs(const float* __restrict__ fs,
                     const float* __restrict__ w1, const float* __restrict__ b1,
                     const float* __restrict__ w2, const float* __restrict__ b2) {
    int b = blockIdx.x;
    int t = threadIdx.x, lane = t & 31, wid = t >> 5;
    __shared__ float tf[256], h1[256];
    if (t < 128) {
        float fr = expf(-9.2103403719761836f * (float)t * (1.0f / 128.0f));
        float arg = fs[b] * fr;
        tf[t] = cosf(arg);
        tf[t + 128] = sinf(arg);
    }
    __syncthreads();
    for (int h = wid; h < 256; h += 8) {
        float4 a0 = *(const float4*)&w1[h * 256 + lane * 8];
        float4 a1 = *(const float4*)&w1[h * 256 + lane * 8 + 4];
        float s = tf[lane*8+0]*a0.x + tf[lane*8+1]*a0.y + tf[lane*8+2]*a0.z + tf[lane*8+3]*a0.w
                + tf[lane*8+4]*a1.x + tf[lane*8+5]*a1.y + tf[lane*8+6]*a1.z + tf[lane*8+7]*a1.w;
#pragma unroll
        for (int d = 16; d > 0; d >>= 1) s += __shfl_down_sync(0xffffffffu, s, d);
        if (lane == 0) { s += b1[h]; h1[h] = s / (1.0f + expf(-s)); }
    }
    __syncthreads();
    for (int h = wid; h < 256; h += 8) {
        float4 a0 = *(const float4*)&w2[h * 256 + lane * 8];
        float4 a1 = *(const float4*)&w2[h * 256 + lane * 8 + 4];
        float s = h1[lane*8+0]*a0.x + h1[lane*8+1]*a0.y + h1[lane*8+2]*a0.z + h1[lane*8+3]*a0.w
                + h1[lane*8+4]*a1.x + h1[lane*8+5]*a1.y + h1[lane*8+6]*a1.z + h1[lane*8+7]*a1.w;
#pragma unroll
        for (int d = 16; d > 0; d >>= 1) s += __shfl_down_sync(0xffffffffu, s, d);
        if (lane == 0) g_fsemb[b * 256 + h] = s + b2[h];
    }
}

// ---------------------------------------------------------------------------
// k_gemm: fused convert + mma.sync bf16 3-term GEMM + tail zeroing.
// Block (512 thr, 16 warps) = (batch, M-tile 128).  N=256 whole.
// 8 fp32 K-chunks of 64 cols; per chunk: cp A fp32 (gathered) + B' [hi|lo],
// convert A -> A'hi/A'lo bf16 smem, 12 MMA k16-stage-terms.
// SMEM (bytes from aligned base AB):
//   0: sBF[256]f  1024: sKL[128]i  2048: A'hi 16K  18432: A'lo 16K
//   34816: Af32 2x32K   100352: B' 2x64K   -> 231424 total
// ---------------------------------------------------------------------------
#define SM_AHI 2048
#define SM_ALO 18432
#define SM_AF  34816
#define SM_BP  100352
#define SMEMSZ (231424 + 128)

__global__ void __launch_bounds__(512, 1)
k_gemm(const float* __restrict__ patches,
       const float* __restrict__ bias, const float* __restrict__ pos,
       float* __restrict__ out_seq) {
    extern __shared__ char dsm[];
    int b  = blockIdx.y;
    int p0 = blockIdx.x * 128;
    int lk = g_lenkeep[b];
    int t = threadIdx.x;

    // ---- pure-zero blocks: whole tile is tail (block-uniform branch) ----
    if (p0 >= lk) {
        float4* dst = (float4*)&out_seq[((size_t)b * LL + p0) * HH];
        float4 z = make_float4(0.f, 0.f, 0.f, 0.f);
#pragma unroll
        for (int i = 0; i < 16; i++) dst[t + i * 512] = z;
        return;
    }

    uint32_t AB = (smem_u32(dsm) + 127u) & ~127u;
    char* ABp = dsm + (AB - smem_u32(dsm));
    float* sBF = (float*)(ABp);
    int*   sKL = (int*)(ABp + 1024);

    int lane = t & 31, wid = t >> 5;
    int wm = wid & 3, wn = wid >> 2;

    if (t < 256) sBF[t] = bias[t] + g_fsemb[b * HH + t];
    if (t < 128) {
        int p = p0 + t;
        sKL[t] = (p < lk) ? g_keptlist[b * LL + p] : 0;
    }
    __syncthreads();   // sKL needed for cp addresses

    // ---- A fp32 cp addresses: 2048 segs (128 rows x 16 segs) / 512 -> 4 ----
    const float* aSrc[4];
    uint32_t aDst[4];
    {
        int s = t & 15;
#pragma unroll
        for (int i = 0; i < 4; i++) {
            int r = (t >> 4) + i * 32;
            aSrc[i] = &patches[((size_t)b * LL + sKL[r]) * PD + s * 4];
            aDst[i] = AB + SM_AF + (uint32_t)(r * 256 + s * 16);
        }
    }
    // ---- B' cp addresses: 4096 segs (512 rows x 8 segs) / 512 -> 8 ----
    uint32_t bDst[8];
    int bSrcOff[8];
    {
#pragma unroll
        for (int i = 0; i < 8; i++) {
            int sid = t + i * 512;
            int r = sid >> 3, s = sid & 7;
            bDst[i] = AB + SM_BP + (uint32_t)(r * 128 + ((s ^ (r & 7)) * 16));
            bSrcOff[i] = r * 64 + s * 8;
        }
    }

    auto copy_chunk = [&](int c) {
        uint32_t ab = (uint32_t)(c & 1) * 32768u;
        uint32_t bb = (uint32_t)(c & 1) * 65536u;
        const __nv_bfloat16* Bg = &g_Bs[c * 32768];
#pragma unroll
        for (int i = 0; i < 4; i++) cp16(aDst[i] + ab, aSrc[i] + c * 64);
#pragma unroll
        for (int i = 0; i < 8; i++) cp16(bDst[i] + bb, Bg + bSrcOff[i]);
        CP_COMMIT();
    };

    // ---- conversion thread mapping (fixed across chunks) ----
    int cvr = t >> 4;               // base row 0..31
    int cvs = t & 15;               // f32 seg (4 floats)
    uint32_t cvSwz = (uint32_t)((((cvs >> 1) ^ (cvr & 7)) * 16) + (cvs & 1) * 8);

    // ---- ldmatrix address components ----
    uint32_t aRB[2], aXP[2];
#pragma unroll
    for (int mt = 0; mt < 2; mt++) {
        int rowA = wm * 32 + mt * 16 + (lane & 15);
        aRB[mt] = AB + SM_AHI + (uint32_t)(rowA * 128);
        aXP[mt] = (uint32_t)((rowA & 7) << 4);
    }
    uint32_t aSG = (uint32_t)((lane >> 4) * 16);
    uint32_t bRB[4], bXP[4];
#pragma unroll
    for (int g = 0; g < 4; g++) {
        int rowB = wn * 64 + g * 16 + ((lane >> 4) << 3) + (lane & 7);
        bRB[g] = AB + SM_BP + (uint32_t)(rowB * 128);
        bXP[g] = (uint32_t)((rowB & 7) << 4);
    }
    uint32_t bSG = (uint32_t)(((lane >> 3) & 1) * 16);

    float acc[2][8][4];
#pragma unroll
    for (int mt = 0; mt < 2; mt++)
#pragma unroll
        for (int nt = 0; nt < 8; nt++)
#pragma unroll
            for (int i = 0; i < 4; i++) acc[mt][nt][i] = 0.f;

    copy_chunk(0);
    copy_chunk(1);

    for (int c = 0; c < NCH; c++) {
        if (c + 2 < NCH) asm volatile("cp.async.wait_group 1;" ::: "memory");
        else             asm volatile("cp.async.wait_group %0;" :: "n"(0) : "memory");
        __syncthreads();

        uint32_t ab = (uint32_t)(c & 1) * 32768u;
        uint32_t bb = (uint32_t)(c & 1) * 65536u;

        // ---- convert A fp32 -> A'hi / A'lo ----
#pragma unroll
        for (int j = 0; j < 4; j++) {
            int r = cvr + j * 32;
            float4 v = *(const float4*)(ABp + SM_AF + ab + r * 256 + cvs * 16);
            __nv_bfloat162 h01 = __float22bfloat162_rn(make_float2(v.x, v.y));
            __nv_bfloat162 h23 = __float22bfloat162_rn(make_float2(v.z, v.w));
            float2 hf01 = __bfloat1622float2(h01);
            float2 hf23 = __bfloat1622float2(h23);
            __nv_bfloat162 l01 = __float22bfloat162_rn(make_float2(v.x - hf01.x, v.y - hf01.y));
            __nv_bfloat162 l23 = __float22bfloat162_rn(make_float2(v.z - hf23.x, v.w - hf23.y));
            uint32_t rb = (uint32_t)(r * 128) + cvSwz;
            *(uint2*)(ABp + SM_AHI + rb) = make_uint2(*(uint32_t*)&h01, *(uint32_t*)&h23);
            *(uint2*)(ABp + SM_ALO + rb) = make_uint2(*(uint32_t*)&l01, *(uint32_t*)&l23);
        }
        __syncthreads();   // A' ready

        // ---- MMA: 4 k16 stages x 3 terms ----
#pragma unroll
        for (int s = 0; s < 4; s++) {
            uint32_t ah[2][4], al[2][4], bf[4][4];
            uint32_t so = (uint32_t)(s * 32);
#pragma unroll
            for (int mt = 0; mt < 2; mt++) {
                uint32_t off = (so + aSG) ^ aXP[mt];
                ldsm4(ah[mt], aRB[mt] + off);
                ldsm4(al[mt], aRB[mt] + 16384u + off);
            }
#pragma unroll
            for (int g = 0; g < 4; g++)
                ldsm4(bf[g], bRB[g] + bb + ((so + bSG) ^ bXP[g]));
#pragma unroll
            for (int mt = 0; mt < 2; mt++)
#pragma unroll
                for (int nt = 0; nt < 8; nt++)
                    mma16816(acc[mt][nt], ah[mt],
                             bf[nt >> 1][(nt & 1) * 2], bf[nt >> 1][(nt & 1) * 2 + 1]);
#pragma unroll
            for (int mt = 0; mt < 2; mt++)
#pragma unroll
                for (int nt = 0; nt < 8; nt++)
                    mma16816(acc[mt][nt], al[mt],
                             bf[nt >> 1][(nt & 1) * 2], bf[nt >> 1][(nt & 1) * 2 + 1]);
#pragma unroll
            for (int g = 0; g < 4; g++)  // Blo region = +32768 (256 rows)
                ldsm4(bf[g], bRB[g] + bb + 32768u + ((so + bSG) ^ bXP[g]));
#pragma unroll
            for (int mt = 0; mt < 2; mt++)
#pragma unroll
                for (int nt = 0; nt < 8; nt++)
                    mma16816(acc[mt][nt], ah[mt],
                             bf[nt >> 1][(nt & 1) * 2], bf[nt >> 1][(nt & 1) * 2 + 1]);
        }
        __syncthreads();   // buffers free
        if (c + 2 < NCH) copy_chunk(c + 2);
    }

    // ---- epilogue: acc + bias + fsemb + pos -> out; tail rows -> 0 ----
#pragma unroll
    for (int mt = 0; mt < 2; mt++) {
        int rbase = wm * 32 + mt * 16 + (lane >> 2);
#pragma unroll
        for (int h = 0; h < 2; h++) {
            int rr = rbase + h * 8;
            int p = p0 + rr;
            int kl = sKL[rr];
            bool ok = p < lk;
            float* orow = &out_seq[(((size_t)b * LL) + p) * HH];
            const float* prow = &pos[(size_t)kl * HH];
#pragma unroll
            for (int nt = 0; nt < 8; nt++) {
                int col = wn * 64 + nt * 8 + (lane & 3) * 2;
                float2 v;
                if (ok) {
                    v.x = acc[mt][nt][h * 2 + 0] + sBF[col]     + prow[col];
                    v.y = acc[mt][nt][h * 2 + 1] + sBF[col + 1] + prow[col + 1];
                } else {
                    v.x = 0.f; v.y = 0.f;
                }
                *(float2*)&orow[col] = v;
            }
        }
    }
}

// ---------------------------------------------------------------------------
extern "C" void kernel_launch(void* const* d_in, const int* in_sizes, int n_in,
                              void* d_out, int out_size) {
    const float* patches = (const float*)d_in[0];
    const int*   sids    = (const int*)  d_in[1];
    const int*   eff     = (const int*)  d_in[2];
    const float* noise   = (const float*)d_in[3];
    const float* fs      = (const float*)d_in[4];
    const float* W       = (const float*)d_in[5];
    const float* bias    = (const float*)d_in[6];
    const float* pos     = (const float*)d_in[7];
    const float* w1      = (const float*)d_in[8];
    const float* b1      = (const float*)d_in[9];
    const float* w2      = (const float*)d_in[10];
    const float* b2      = (const float*)d_in[11];
    float* out = (float*)d_out;

    cudaFuncSetAttribute(k_gemm, cudaFuncAttributeMaxDynamicSharedMemorySize, SMEMSZ);

    k_prep<<<BB, 1024>>>(sids, eff, noise, out);
    k_convW<<<64, 256>>>(W);
    k_fs<<<BB, 256>>>(fs, w1, b1, w2, b2);
    k_gemm<<<dim3(32, BB), 512, SMEMSZ>>>(patches, bias, pos, out);

    (void)in_sizes; (void)n_in; (void)out_size;
}

// round 8
// speedup vs baseline: 3.5543x; 1.3723x over previous
#include <cuda_runtime.h>
#include <cuda_bf16.h>
#include <math.h>
#include <stdint.h>

#define BB 16
#define LL 4096
#define PD 512
#define HH 256
#define NB 2048            // rank buckets
#define NCH 8              // fp32 K chunks of 64

// ---------------------------------------------------------------------------
// scratch (static device memory — no allocations allowed)
// ---------------------------------------------------------------------------
__device__ int   g_keptlist[BB * LL];
__device__ int   g_lenkeep[BB];
__device__ float g_fsemb[BB * HH];
__device__ float g_h1[BB * HH];
// per chunk c: [Bhi 256x64 | Blo 256x64] flat = 32768 bf16; 8 chunks = 512 KB
__device__ __align__(1024) __nv_bfloat16 g_Bs[8 * 32768];

// ---------------------------------------------------------------------------
// PTX helpers (plain sm_80/90 PTX — no 'a'-gated instructions)
// ---------------------------------------------------------------------------
__device__ __forceinline__ uint32_t smem_u32(const void* p) {
    uint32_t a;
    asm("{ .reg .u64 t; cvta.to.shared.u64 t, %1; cvt.u32.u64 %0, t; }" : "=r"(a) : "l"(p));
    return a;
}
__device__ __forceinline__ void cp16(uint32_t s, const void* g) {
    asm volatile("cp.async.cg.shared.global [%0], [%1], 16;" :: "r"(s), "l"(g));
}
#define CP_COMMIT() asm volatile("cp.async.commit_group;" ::: "memory")

__device__ __forceinline__ void ldsm4(uint32_t* r, uint32_t a) {
    asm volatile("ldmatrix.sync.aligned.m8n8.x4.shared.b16 {%0,%1,%2,%3}, [%4];"
                 : "=r"(r[0]), "=r"(r[1]), "=r"(r[2]), "=r"(r[3]) : "r"(a));
}
__device__ __forceinline__ void mma16816(float* d, const uint32_t* a,
                                         uint32_t b0, uint32_t b1) {
    asm volatile(
        "mma.sync.aligned.m16n8k16.row.col.f32.bf16.bf16.f32 "
        "{%0,%1,%2,%3}, {%4,%5,%6,%7}, {%8,%9}, {%0,%1,%2,%3};"
        : "+f"(d[0]), "+f"(d[1]), "+f"(d[2]), "+f"(d[3])
        : "r"(a[0]), "r"(a[1]), "r"(a[2]), "r"(a[3]), "r"(b0), "r"(b1));
}

// ---------------------------------------------------------------------------
// block-wide exclusive scan over one int per thread (1024 threads)
// ---------------------------------------------------------------------------
__device__ __forceinline__ int block_exscan(int v, int* wsum) {
    int lane = threadIdx.x & 31, wid = threadIdx.x >> 5;
    int inc = v;
#pragma unroll
    for (int d = 1; d < 32; d <<= 1) {
        int u = __shfl_up_sync(0xffffffffu, inc, d);
        if (lane >= d) inc += u;
    }
    if (lane == 31) wsum[wid] = inc;
    __syncthreads();
    if (wid == 0) {
        int s = wsum[lane];
#pragma unroll
        for (int d = 1; d < 32; d <<= 1) {
            int u = __shfl_up_sync(0xffffffffu, s, d);
            if (lane >= d) s += u;
        }
        wsum[lane] = s;
    }
    __syncthreads();
    return ((wid > 0) ? wsum[wid - 1] : 0) + (inc - v);
}

// ---------------------------------------------------------------------------
// k_prep: fused setup + bucket-rank + scan.  One block (1024 thr) per row.
// ---------------------------------------------------------------------------
__global__ void __launch_bounds__(1024, 1)
k_prep(const int* __restrict__ sids, const int* __restrict__ eff_lens,
       const float* __restrict__ noise, float* __restrict__ out) {
    __shared__ unsigned long long s_keys[LL];
    __shared__ int s_hist[NB + 1];
    __shared__ int s_wsum[32];
    __shared__ int s_ns;

    int b = blockIdx.x;
    int t = threadIdx.x;
    int eff = eff_lens[b];
    int base = t * 4;

    s_hist[t] = 0;
    if (t < NB + 1 - 1024) s_hist[1024 + t] = 0;
    if (t == 0) { s_hist[NB] = 0; s_ns = 0; }

    int4  sd4 = *(const int4*)  &sids [b * LL + base];
    float4 nz4 = *(const float4*)&noise[b * LL + base];
    int sm1 = (base >= 1) ? sids[b * LL + base - 1] : -1;
    int sm2 = (base >= 2) ? sids[b * LL + base - 2] : -1;
    __syncthreads();

    int   sd[6] = {sm2, sm1, sd4.x, sd4.y, sd4.z, sd4.w};
    float nz[4] = {nz4.x, nz4.y, nz4.z, nz4.w};

    unsigned long long key[4];
    int bid[4], slot[4];
    int nseg = 0;
#pragma unroll
    for (int i = 0; i < 4; i++) {
        int l = base + i;
        bool valid = l < eff;
        bool seg = valid && (sd[i + 2] != sd[i + 1]);
        bool fst = valid && (l >= 1) && (sd[i + 1] != sd[i]);
        nseg += seg ? 1 : 0;
        float v = (seg || fst) ? 0.0f : nz[i];
        unsigned int bits = __float_as_uint(v);
        key[i] = ((unsigned long long)bits << 12) | (unsigned)l;
        bid[i] = min(NB - 1, (int)(v * (float)NB));
        if (valid) slot[i] = atomicAdd(&s_hist[bid[i]], 1);
    }
    {
        int v = nseg;
#pragma unroll
        for (int d = 16; d > 0; d >>= 1) v += __shfl_down_sync(0xffffffffu, v, d);
        if ((t & 31) == 0 && v) atomicAdd(&s_ns, v);
    }
    __syncthreads();

    int ns = s_ns;
    int lk = 2 * ns + (int)((float)(eff - 2 * ns) * 0.25f);

    int c0 = s_hist[2 * t], c1 = s_hist[2 * t + 1];
    int ex = block_exscan(c0 + c1, s_wsum);
    s_hist[2 * t] = ex;
    s_hist[2 * t + 1] = ex + c0;
    if (t == 1023) s_hist[NB] = ex + c0 + c1;
    __syncthreads();

#pragma unroll
    for (int i = 0; i < 4; i++) {
        int l = base + i;
        if (l < eff) s_keys[s_hist[bid[i]] + slot[i]] = key[i];
    }
    __syncthreads();

    int r[4];
    bool kept[4];
    int cnt = 0;
#pragma unroll
    for (int i = 0; i < 4; i++) {
        int l = base + i;
        if (l < eff) {
            int lo = s_hist[bid[i]], hi = s_hist[bid[i] + 1];
            int c = 0;
            for (int m = lo; m < hi; m++) c += (s_keys[m] < key[i]) ? 1 : 0;
            r[i] = lo + c;
        } else {
            r[i] = l;
        }
        kept[i] = (l < eff) && (r[i] < lk);
        cnt += kept[i] ? 1 : 0;
    }
    __syncthreads();

    int p = block_exscan(cnt, s_wsum);

    const size_t O1 = (size_t)BB * LL * HH;
    const size_t O2 = O1 + (size_t)BB * LL;
    const size_t O3 = O2 + (size_t)BB * LL;
    float* mae = out + O1 + (size_t)b * LL;
    float* rst = out + O2 + (size_t)b * LL;
    float* unm = out + O3 + (size_t)b * LL;

#pragma unroll
    for (int i = 0; i < 4; i++) {
        int l = base + i;
        mae[l] = (l < eff && !kept[i]) ? 1.0f : 0.0f;
        rst[l] = (float)(kept[i] ? p : r[i]);
        if (kept[i]) {
            g_keptlist[b * LL + p] = l;
            unm[p] = (float)sd[i + 2];
            p++;
        }
        if (l >= lk) unm[l] = -1.0f;
    }
    if (t == 0) g_lenkeep[b] = lk;
}

// ---------------------------------------------------------------------------
// k_convW: W fp32 -> per-chunk [Bhi | Blo] bf16.  16384 threads.
// ---------------------------------------------------------------------------
__global__ void k_convW(const float* __restrict__ W) {
    int gid = blockIdx.x * 256 + threadIdx.x;   // 16384
    int row = gid >> 6;          // 0..255
    int g   = gid & 63;          // col group of 8 f32
    int c   = g >> 3;            // chunk
    int cc  = (g & 7) * 8;       // col within chunk
    float4 v0 = *(const float4*)&W[(size_t)row * PD + g * 8];
    float4 v1 = *(const float4*)&W[(size_t)row * PD + g * 8 + 4];
    float a[8] = {v0.x, v0.y, v0.z, v0.w, v1.x, v1.y, v1.z, v1.w};
    __align__(16) __nv_bfloat16 oh[8], ol[8];
#pragma unroll
    for (int i = 0; i < 8; i++) {
        __nv_bfloat16 h = __float2bfloat16_rn(a[i]);
        oh[i] = h;
        ol[i] = __float2bfloat16_rn(a[i] - __bfloat162float(h));
    }
    *(uint4*)&g_Bs[c * 32768 + row * 64 + cc]         = *(const uint4*)oh;
    *(uint4*)&g_Bs[c * 32768 + 16384 + row * 64 + cc] = *(const uint4*)ol;
}

// ---------------------------------------------------------------------------
// k_fs1 / k_fs2: timestep MLP split at the layer boundary.
// grid (BB, 8): block computes 32 h outputs; each warp 4 h (warp-per-output).
// ---------------------------------------------------------------------------
__global__ void k_fs1(const float* __restrict__ fs,
                      const float* __restrict__ w1, const float* __restrict__ b1) {
    int b = blockIdx.x;
    int t = threadIdx.x, lane = t & 31, wid = t >> 5;
    __shared__ float tf[256];
    if (t < 128) {
        float fr = expf(-9.2103403719761836f * (float)t * (1.0f / 128.0f));
        float arg = fs[b] * fr;
        tf[t] = cosf(arg);
        tf[t + 128] = sinf(arg);
    }
    __syncthreads();
#pragma unroll
    for (int j = 0; j < 4; j++) {
        int h = blockIdx.y * 32 + wid * 4 + j;
        float4 a0 = *(const float4*)&w1[h * 256 + lane * 8];
        float4 a1 = *(const float4*)&w1[h * 256 + lane * 8 + 4];
        float s = tf[lane*8+0]*a0.x + tf[lane*8+1]*a0.y + tf[lane*8+2]*a0.z + tf[lane*8+3]*a0.w
                + tf[lane*8+4]*a1.x + tf[lane*8+5]*a1.y + tf[lane*8+6]*a1.z + tf[lane*8+7]*a1.w;
#pragma unroll
        for (int d = 16; d > 0; d >>= 1) s += __shfl_down_sync(0xffffffffu, s, d);
        if (lane == 0) { s += b1[h]; g_h1[b * 256 + h] = s / (1.0f + expf(-s)); }
    }
}

__global__ void k_fs2(const float* __restrict__ w2, const float* __restrict__ b2) {
    int b = blockIdx.x;
    int t = threadIdx.x, lane = t & 31, wid = t >> 5;
    __shared__ float h1[256];
    h1[t] = g_h1[b * 256 + t];
    __syncthreads();
#pragma unroll
    for (int j = 0; j < 4; j++) {
        int h = blockIdx.y * 32 + wid * 4 + j;
        float4 a0 = *(const float4*)&w2[h * 256 + lane * 8];
        float4 a1 = *(const float4*)&w2[h * 256 + lane * 8 + 4];
        float s = h1[lane*8+0]*a0.x + h1[lane*8+1]*a0.y + h1[lane*8+2]*a0.z + h1[lane*8+3]*a0.w
                + h1[lane*8+4]*a1.x + h1[lane*8+5]*a1.y + h1[lane*8+6]*a1.z + h1[lane*8+7]*a1.w;
#pragma unroll
        for (int d = 16; d > 0; d >>= 1) s += __shfl_down_sync(0xffffffffu, s, d);
        if (lane == 0) g_fsemb[b * 256 + h] = s + b2[h];
    }
}

// ---------------------------------------------------------------------------
// k_gemm: fused convert + mma.sync bf16 3-term GEMM + tail zeroing.
// Block (512 thr, 16 warps) = (batch, M-tile 128).  N=256 whole.
// 8 fp32 K-chunks of 64 cols.  A gathered via direct LDG -> regs -> converted
// into double-buffered A'hi/lo smem inside the MMA region; B' via double-
// buffered cp.async.  ONE sync per chunk.
// SMEM from 128-aligned base AB:
//   0: sBF[256]f  1024: sKL[128]i
//   2048:  A' buf x2 (each: hi 16K @+0, lo 16K @+16384) = 64 KB
//   67584: B' buf x2 (each: hi 32K @+0, lo 32K @+32768) = 128 KB
// ---------------------------------------------------------------------------
#define SM_AP 2048
#define SM_BP 67584
#define SMEMSZ (198656 + 1024)

__global__ void __launch_bounds__(512, 1)
k_gemm(const float* __restrict__ patches,
       const float* __restrict__ bias, const float* __restrict__ pos,
       float* __restrict__ out_seq) {
    extern __shared__ char dsm[];
    int b  = blockIdx.y;
    int p0 = blockIdx.x * 128;
    int lk = g_lenkeep[b];
    int t = threadIdx.x;

    // ---- pure-zero blocks: whole tile is tail (block-uniform branch) ----
    if (p0 >= lk) {
        float4* dst = (float4*)&out_seq[((size_t)b * LL + p0) * HH];
        float4 z = make_float4(0.f, 0.f, 0.f, 0.f);
#pragma unroll
        for (int i = 0; i < 16; i++) dst[t + i * 512] = z;
        return;
    }

    uint32_t AB = (smem_u32(dsm) + 127u) & ~127u;
    char* ABp = dsm + (AB - smem_u32(dsm));
    float* sBF = (float*)(ABp);
    int*   sKL = (int*)(ABp + 1024);

    int lane = t & 31, wid = t >> 5;
    int wm = wid & 3, wn = wid >> 2;

    if (t < 256) sBF[t] = bias[t] + g_fsemb[b * HH + t];
    if (t < 128) {
        int p = p0 + t;
        sKL[t] = (p < lk) ? g_keptlist[b * LL + p] : 0;
    }
    __syncthreads();   // sKL needed for LDG addresses

    // ---- A LDG mapping: row = t>>2, 16 f32 at col (t&3)*16 ----
    int cvr = t >> 2;
    int cvc = t & 3;
    const float* aPtr = &patches[((size_t)b * LL + sKL[cvr]) * PD + cvc * 16];
    // A' store: hi 2 STS.128 at swizzled segs {cvc*2, cvc*2+1} ^ (row&7); lo same
    uint32_t aStBase = (uint32_t)(SM_AP + cvr * 128);
    uint32_t aSeg0 = (uint32_t)(((cvc * 2)     ^ (cvr & 7)) * 16);
    uint32_t aSeg1 = (uint32_t)(((cvc * 2 + 1) ^ (cvr & 7)) * 16);

    // ---- B' cp addresses: 4096 segs (512 rows x 8 segs) / 512 -> 8 ----
    uint32_t bDst[8];
    int bSrcOff[8];
#pragma unroll
    for (int i = 0; i < 8; i++) {
        int sid = t + i * 512;
        int r = sid >> 3, s = sid & 7;
        bDst[i] = AB + SM_BP + (uint32_t)(r * 128 + ((s ^ (r & 7)) * 16));
        bSrcOff[i] = r * 64 + s * 8;
    }

    // ---- ldmatrix address components ----
    uint32_t aRB[2], aXP[2];
#pragma unroll
    for (int mt = 0; mt < 2; mt++) {
        int rowA = wm * 32 + mt * 16 + (lane & 15);
        aRB[mt] = AB + SM_AP + (uint32_t)(rowA * 128);
        aXP[mt] = (uint32_t)((rowA & 7) << 4);
    }
    uint32_t aSG = (uint32_t)((lane >> 4) * 16);
    uint32_t bRB[4], bXP[4];
#pragma unroll
    for (int g = 0; g < 4; g++) {
        int rowB = wn * 64 + g * 16 + ((lane >> 4) << 3) + (lane & 7);
        bRB[g] = AB + SM_BP + (uint32_t)(rowB * 128);
        bXP[g] = (uint32_t)((rowB & 7) << 4);
    }
    uint32_t bSG = (uint32_t)(((lane >> 3) & 1) * 16);

    float acc[2][8][4];
#pragma unroll
    for (int mt = 0; mt < 2; mt++)
#pragma unroll
        for (int nt = 0; nt < 8; nt++)
#pragma unroll
            for (int i = 0; i < 4; i++) acc[mt][nt][i] = 0.f;

    float4 av[4];

    auto cp_B = [&](int c) {
        uint32_t bb = (uint32_t)(c & 1) * 65536u;
        const __nv_bfloat16* Bg = &g_Bs[c * 32768];
#pragma unroll
        for (int i = 0; i < 8; i++) cp16(bDst[i] + bb, Bg + bSrcOff[i]);
        CP_COMMIT();
    };
    auto ldg_A = [&](int c) {
#pragma unroll
        for (int i = 0; i < 4; i++)
            av[i] = __ldg((const float4*)(aPtr + c * 64 + i * 4));
    };
    auto conv_A = [&](int c) {
        uint32_t hi[8], lo[8];
#pragma unroll
        for (int i = 0; i < 4; i++) {
            float4 v = av[i];
            __nv_bfloat162 h01 = __float22bfloat162_rn(make_float2(v.x, v.y));
            __nv_bfloat162 h23 = __float22bfloat162_rn(make_float2(v.z, v.w));
            float2 hf01 = __bfloat1622float2(h01);
            float2 hf23 = __bfloat1622float2(h23);
            __nv_bfloat162 l01 = __float22bfloat162_rn(make_float2(v.x - hf01.x, v.y - hf01.y));
            __nv_bfloat162 l23 = __float22bfloat162_rn(make_float2(v.z - hf23.x, v.w - hf23.y));
            hi[i * 2]     = *(uint32_t*)&h01;
            hi[i * 2 + 1] = *(uint32_t*)&h23;
            lo[i * 2]     = *(uint32_t*)&l01;
            lo[i * 2 + 1] = *(uint32_t*)&l23;
        }
        uint32_t base = aStBase + (uint32_t)(c & 1) * 32768u;
        *(uint4*)(ABp + base + aSeg0)         = make_uint4(hi[0], hi[1], hi[2], hi[3]);
        *(uint4*)(ABp + base + aSeg1)         = make_uint4(hi[4], hi[5], hi[6], hi[7]);
        *(uint4*)(ABp + base + 16384 + aSeg0) = make_uint4(lo[0], lo[1], lo[2], lo[3]);
        *(uint4*)(ABp + base + 16384 + aSeg1) = make_uint4(lo[4], lo[5], lo[6], lo[7]);
    };

    // ---- prologue: B'(0) in flight; convert A(0) ----
    cp_B(0);
    ldg_A(0);
    conv_A(0);
    asm volatile("cp.async.wait_group 0;" ::: "memory");
    __syncthreads();

    for (int c = 0; c < NCH; c++) {
        uint32_t ab = (uint32_t)(c & 1) * 32768u;
        uint32_t bb = (uint32_t)(c & 1) * 65536u;
        if (c + 1 < NCH) { cp_B(c + 1); ldg_A(c + 1); }

        // ---- MMA: 4 k16 stages x 3 terms; convert(c+1) inserted mid-stream ----
#pragma unroll
        for (int s = 0; s < 4; s++) {
            uint32_t ah[2][4], al[2][4], bf[4][4];
            uint32_t so = (uint32_t)(s * 32);
#pragma unroll
            for (int mt = 0; mt < 2; mt++) {
                uint32_t off = (so + aSG) ^ aXP[mt];
                ldsm4(ah[mt], aRB[mt] + ab + off);
                ldsm4(al[mt], aRB[mt] + ab + 16384u + off);
            }
#pragma unroll
            for (int g = 0; g < 4; g++)
                ldsm4(bf[g], bRB[g] + bb + ((so + bSG) ^ bXP[g]));
#pragma unroll
            for (int mt = 0; mt < 2; mt++)
#pragma unroll
                for (int nt = 0; nt < 8; nt++)
                    mma16816(acc[mt][nt], ah[mt],
                             bf[nt >> 1][(nt & 1) * 2], bf[nt >> 1][(nt & 1) * 2 + 1]);
            if (s == 0 && c + 1 < NCH) conv_A(c + 1);   // overlaps tensor work
#pragma unroll
            for (int mt = 0; mt < 2; mt++)
#pragma unroll
                for (int nt = 0; nt < 8; nt++)
                    mma16816(acc[mt][nt], al[mt],
                             bf[nt >> 1][(nt & 1) * 2], bf[nt >> 1][(nt & 1) * 2 + 1]);
#pragma unroll
            for (int g = 0; g < 4; g++)  // Blo region = +32768
                ldsm4(bf[g], bRB[g] + bb + 32768u + ((so + bSG) ^ bXP[g]));
#pragma unroll
            for (int mt = 0; mt < 2; mt++)
#pragma unroll
                for (int nt = 0; nt < 8; nt++)
                    mma16816(acc[mt][nt], ah[mt],
                             bf[nt >> 1][(nt & 1) * 2], bf[nt >> 1][(nt & 1) * 2 + 1]);
        }
        asm volatile("cp.async.wait_group 0;" ::: "memory");
        __syncthreads();
    }

    // ---- epilogue: acc + bias + fsemb + pos -> out; tail rows -> 0 ----
#pragma unroll
    for (int mt = 0; mt < 2; mt++) {
        int rbase = wm * 32 + mt * 16 + (lane >> 2);
#pragma unroll
        for (int h = 0; h < 2; h++) {
            int rr = rbase + h * 8;
            int p = p0 + rr;
            int kl = sKL[rr];
            bool ok = p < lk;
            float* orow = &out_seq[(((size_t)b * LL) + p) * HH];
            const float* prow = &pos[(size_t)kl * HH];
#pragma unroll
            for (int nt = 0; nt < 8; nt++) {
                int col = wn * 64 + nt * 8 + (lane & 3) * 2;
                float2 v;
                if (ok) {
                    v.x = acc[mt][nt][h * 2 + 0] + sBF[col]     + prow[col];
                    v.y = acc[mt][nt][h * 2 + 1] + sBF[col + 1] + prow[col + 1];
                } else {
                    v.x = 0.f; v.y = 0.f;
                }
                *(float2*)&orow[col] = v;
            }
        }
    }
}

// ---------------------------------------------------------------------------
extern "C" void kernel_launch(void* const* d_in, const int* in_sizes, int n_in,
                              void* d_out, int out_size) {
    const float* patches = (const float*)d_in[0];
    const int*   sids    = (const int*)  d_in[1];
    const int*   eff     = (const int*)  d_in[2];
    const float* noise   = (const float*)d_in[3];
    const float* fs      = (const float*)d_in[4];
    const float* W       = (const float*)d_in[5];
    const float* bias    = (const float*)d_in[6];
    const float* pos     = (const float*)d_in[7];
    const float* w1      = (const float*)d_in[8];
    const float* b1      = (const float*)d_in[9];
    const float* w2      = (const float*)d_in[10];
    const float* b2      = (const float*)d_in[11];
    float* out = (float*)d_out;

    cudaFuncSetAttribute(k_gemm, cudaFuncAttributeMaxDynamicSharedMemorySize, SMEMSZ);

    k_prep<<<BB, 1024>>>(sids, eff, noise, out);
    k_convW<<<64, 256>>>(W);
    k_fs1<<<dim3(BB, 8), 256>>>(fs, w1, b1);
    k_fs2<<<dim3(BB, 8), 256>>>(w2, b2);
    k_gemm<<<dim3(32, BB), 512, SMEMSZ>>>(patches, bias, pos, out);

    (void)in_sizes; (void)n_in; (void)out_size;
}